// round 3
// baseline (speedup 1.0000x reference)
#include <cuda_runtime.h>
#include <cuda_bf16.h>
#include <cstdint>
#include <math.h>

// Problem constants (CTC_72000831750194): B=32, T=1000, V=1024, L=128
#define CB 32
#define CT 1000
#define CV 1024
#define CL 128
#define CS (2 * CL + 1)   // 257
#define PSTR 132          // per-(b,t) prob row: [p_blank, pad, pad, pad, p_lab0..p_lab127]

// Scratch (allocation-free rule: __device__ globals)
__device__ float g_p[(size_t)CB * CT * PSTR];   // linear softmax probs at blank+labels
__device__ float g_loss[CB];

// ---------------------------------------------------------------------------
// Kernel 1: warp-per-row softmax. Each warp: 32 lanes x 8 float4 = 1024 floats.
//   g_p[row][0]   = softmax(row)[0]          (blank)
//   g_p[row][4+k] = softmax(row)[ys[b][k]]   (k = 0..127)
// ---------------------------------------------------------------------------
__global__ void __launch_bounds__(256) ctc_p_kernel(
    const float* __restrict__ hs, const int* __restrict__ ys)
{
    const int warp = threadIdx.x >> 5;
    const int lane = threadIdx.x & 31;
    const int row  = blockIdx.x * 8 + warp;      // grid = B*T/8
    const int b    = row / CT;

    const float*  rp  = hs + (size_t)row * CV;
    const float4* rp4 = reinterpret_cast<const float4*>(rp);

    float4 v[8];
    #pragma unroll
    for (int i = 0; i < 8; ++i) v[i] = rp4[i * 32 + lane];

    float m = -1e30f;
    #pragma unroll
    for (int i = 0; i < 8; ++i)
        m = fmaxf(m, fmaxf(fmaxf(v[i].x, v[i].y), fmaxf(v[i].z, v[i].w)));
    #pragma unroll
    for (int o = 16; o > 0; o >>= 1)
        m = fmaxf(m, __shfl_xor_sync(0xffffffffu, m, o));

    float s = 0.f;
    #pragma unroll
    for (int i = 0; i < 8; ++i)
        s += __expf(v[i].x - m) + __expf(v[i].y - m) +
             __expf(v[i].z - m) + __expf(v[i].w - m);
    #pragma unroll
    for (int o = 16; o > 0; o >>= 1)
        s += __shfl_xor_sync(0xffffffffu, s, o);

    const float inv = 1.0f / s;

    float* op = g_p + (size_t)row * PSTR;
    #pragma unroll
    for (int c = 0; c < 4; ++c) {
        const int k   = c * 32 + lane;
        const int lab = ys[b * CL + k];
        op[4 + k] = __expf(rp[lab] - m) * inv;
    }
    if (lane == 0) op[0] = __expf(rp[0] - m) * inv;
}

// ---------------------------------------------------------------------------
// Kernel 2: alpha recursion, LINEAR domain, FP64, one warp per batch element.
// Lane l owns states 8l..8l+7 (a[0..7]); lane 31 also owns s=256 (a[8]).
// a[8] on other lanes is a harmless unused shadow (never feeds real states).
// Renormalize by an exact power of two every 8 steps (Eacc accumulates it).
// ---------------------------------------------------------------------------
__device__ __forceinline__ void step_d(
    double a[9], float4 plf, float pbf, const double mk[4], int lane)
{
    const double pb = (double)pbf;
    const double p0 = (double)plf.x, p1 = (double)plf.y;
    const double p2 = (double)plf.z, p3 = (double)plf.w;

    double s1 = __shfl_up_sync(0xffffffffu, a[7], 1);   // old state 8l-1
    if (lane == 0) s1 = 0.0;

    // even states s=8l+2j (blank): (a[s] + a[s-1]) * p_blank
    // odd  states s=8l+2j+1 (label k=4l+j): (a[s] + a[s-1] + mk*a[s-2]) * p_k
    const double n0 = (a[0] + s1) * pb;
    const double n1 = (a[1] + a[0] + mk[0] * s1)   * p0;
    const double n2 = (a[2] + a[1]) * pb;
    const double n3 = (a[3] + a[2] + mk[1] * a[1]) * p1;
    const double n4 = (a[4] + a[3]) * pb;
    const double n5 = (a[5] + a[4] + mk[2] * a[3]) * p2;
    const double n6 = (a[6] + a[5]) * pb;
    const double n7 = (a[7] + a[6] + mk[3] * a[5]) * p3;
    const double n8 = (a[8] + a[7]) * pb;               // state 256 on lane 31
    a[0] = n0; a[1] = n1; a[2] = n2; a[3] = n3; a[4] = n4;
    a[5] = n5; a[6] = n6; a[7] = n7; a[8] = n8;
}

__global__ void __launch_bounds__(32) ctc_alpha_kernel(
    const int* __restrict__ h_lens, const int* __restrict__ ys,
    const int* __restrict__ ys_lens)
{
    const int b    = blockIdx.x;
    const int lane = threadIdx.x;
    int Tb = h_lens[b];
    if (Tb > CT) Tb = CT;
    const float* pb = g_p + (size_t)b * CT * PSTR;
    const unsigned FULL = 0xffffffffu;

    // skip masks (scalar loads): odd state s=2k+1 skips iff k>=1 && ys[k]!=ys[k-1]
    double mk[4];
    #pragma unroll
    for (int j = 0; j < 4; ++j) {
        const int k = 4 * lane + j;
        mk[j] = (k >= 1 && ys[b * CL + k] != ys[b * CL + k - 1]) ? 1.0 : 0.0;
    }

    // alpha at t=0
    double a[9];
    #pragma unroll
    for (int j = 0; j < 9; ++j) a[j] = 0.0;
    if (lane == 0) { a[0] = (double)pb[0]; a[1] = (double)pb[4]; }

    int Eacc = 0;

    // 8-step double buffer: cur preloaded with rows 1..8, nxt fetched each iter
    float4 curL[8], nxtL[8];
    float  curB[8], nxtB[8];
    #pragma unroll
    for (int k = 0; k < 8; ++k) {
        int t = 1 + k; if (t > CT - 1) t = CT - 1;
        const float* r = pb + (size_t)t * PSTR;
        curL[k] = reinterpret_cast<const float4*>(r + 4)[lane];
        curB[k] = r[0];
    }

    for (int t0 = 1; t0 < Tb; t0 += 8) {
        // prefetch next chunk (rows t0+8 .. t0+15, clamped)
        #pragma unroll
        for (int k = 0; k < 8; ++k) {
            int t = t0 + 8 + k; if (t > CT - 1) t = CT - 1;
            const float* r = pb + (size_t)t * PSTR;
            nxtL[k] = reinterpret_cast<const float4*>(r + 4)[lane];
            nxtB[k] = r[0];
        }

        // consume current chunk: steps t = t0 .. t0+7
        #pragma unroll
        for (int k = 0; k < 8; ++k) {
            if (t0 + k < Tb) step_d(a, curL[k], curB[k], mk, lane);
        }

        // renorm by exact power of two (uniform across warp)
        double m = a[0];
        #pragma unroll
        for (int j = 1; j < 9; ++j) m = fmax(m, a[j]);
        #pragma unroll
        for (int o = 16; o > 0; o >>= 1)
            m = fmax(m, __shfl_xor_sync(FULL, m, o));
        int e; frexp(m, &e);                 // m = f * 2^e, f in [0.5, 1)
        const double sc = ldexp(1.0, -e);
        #pragma unroll
        for (int j = 0; j < 9; ++j) a[j] *= sc;
        Eacc += e;                           // true = stored * 2^Eacc

        #pragma unroll
        for (int k = 0; k < 8; ++k) { curL[k] = nxtL[k]; curB[k] = nxtB[k]; }
    }

    // final: loss = -(log(alpha[2L] + alpha[2L-1]) + Eacc*ln2) / L
    __shared__ double sh[CS];
    #pragma unroll
    for (int j = 0; j < 8; ++j) sh[8 * lane + j] = a[j];
    if (lane == 31) sh[256] = a[8];
    __syncwarp();
    if (lane == 0) {
        const int    yl = ys_lens[b];
        const double s  = sh[2 * yl] + sh[2 * yl - 1];
        g_loss[b] = (float)(-(log(s) + (double)Eacc * 0.6931471805599453) / (double)yl);
    }
}

// ---------------------------------------------------------------------------
// Kernel 3: mean over batch -> scalar output
// ---------------------------------------------------------------------------
__global__ void ctc_reduce_kernel(float* __restrict__ out)
{
    float v = (threadIdx.x < CB) ? g_loss[threadIdx.x] : 0.f;
    #pragma unroll
    for (int o = 16; o > 0; o >>= 1)
        v += __shfl_xor_sync(0xffffffffu, v, o);
    if (threadIdx.x == 0) out[0] = v / (float)CB;
}

extern "C" void kernel_launch(void* const* d_in, const int* in_sizes, int n_in,
                              void* d_out, int out_size)
{
    const float* hs      = (const float*)d_in[0];  // (B, T, V)
    const int*   h_lens  = (const int*)  d_in[1];  // (B,)
    const int*   ys      = (const int*)  d_in[2];  // (B, L)
    const int*   ys_lens = (const int*)  d_in[3];  // (B,)
    float*       out     = (float*)      d_out;

    ctc_p_kernel<<<CB * CT / 8, 256>>>(hs, ys);
    ctc_alpha_kernel<<<CB, 32>>>(h_lens, ys, ys_lens);
    ctc_reduce_kernel<<<1, 32>>>(out);
}

// round 6
// speedup vs baseline: 8.9454x; 8.9454x over previous
#include <cuda_runtime.h>
#include <cuda_bf16.h>
#include <cstdint>
#include <math.h>

// Problem constants (CTC_72000831750194): B=32, T=1000, V=1024, L=128
#define CB 32
#define CT 1000
#define CV 1024
#define CL 128
#define CS (2 * CL + 1)   // 257
#define PSTR 132          // per-(b,t) prob row: [p_blank, pad, pad, pad, p_lab0..p_lab127]
#define FULLM 0xffffffffu

// Scratch (allocation-free rule: __device__ globals)
__device__ float g_p[(size_t)CB * CT * PSTR];   // linear softmax probs at blank+labels
__device__ float g_loss[CB];

// ---------------------------------------------------------------------------
// Kernel 1: warp-per-row softmax (R3 version: 26.6us, 66.8% DRAM).
//   g_p[row][0]   = softmax(row)[0]          (blank)
//   g_p[row][4+k] = softmax(row)[ys[b][k]]   (k = 0..127)
// ---------------------------------------------------------------------------
__global__ void __launch_bounds__(256) ctc_p_kernel(
    const float* __restrict__ hs, const int* __restrict__ ys)
{
    const int warp = threadIdx.x >> 5;
    const int lane = threadIdx.x & 31;
    const int row  = blockIdx.x * 8 + warp;      // grid = B*T/8
    const int b    = row / CT;

    const float*  rp  = hs + (size_t)row * CV;
    const float4* rp4 = reinterpret_cast<const float4*>(rp);

    float4 v[8];
    #pragma unroll
    for (int i = 0; i < 8; ++i) v[i] = rp4[i * 32 + lane];

    float m = -1e30f;
    #pragma unroll
    for (int i = 0; i < 8; ++i)
        m = fmaxf(m, fmaxf(fmaxf(v[i].x, v[i].y), fmaxf(v[i].z, v[i].w)));
    #pragma unroll
    for (int o = 16; o > 0; o >>= 1)
        m = fmaxf(m, __shfl_xor_sync(FULLM, m, o));

    float s = 0.f;
    #pragma unroll
    for (int i = 0; i < 8; ++i)
        s += __expf(v[i].x - m) + __expf(v[i].y - m) +
             __expf(v[i].z - m) + __expf(v[i].w - m);
    #pragma unroll
    for (int o = 16; o > 0; o >>= 1)
        s += __shfl_xor_sync(FULLM, s, o);

    const float inv = 1.0f / s;

    float* op = g_p + (size_t)row * PSTR;
    #pragma unroll
    for (int c = 0; c < 4; ++c) {
        const int k   = c * 32 + lane;
        const int lab = ys[b * CL + k];
        op[4 + k] = __expf(rp[lab] - m) * inv;
    }
    if (lane == 0) op[0] = __expf(rp[0] - m) * inv;
}

// ---------------------------------------------------------------------------
// Kernel 2: alpha recursion, LINEAR fp32, GLOBAL warp frame biased high.
// One warp per batch element. Lane l owns states 8l..8l+7 (a[0..7]);
// lane 31 also owns s=256 (a[8]; shadow elsewhere, never crosses lanes).
// Every 4 steps: warp-max renormalized to ~2^118 (exact power-of-two scale,
// applied as two representable factors). true_alpha = stored * 2^Eacc.
// Window below max ~145-169 nats >> ~110-nat frontier deficit.
// ---------------------------------------------------------------------------
__device__ __forceinline__ void step_f(
    float a[9], float4 pl, float pbk, const float mk[4], int lane)
{
    float s1 = __shfl_up_sync(FULLM, a[7], 1);   // old state 8l-1
    if (lane == 0) s1 = 0.f;

    const float n0 = (a[0] + s1) * pbk;                     // s=8l   (blank)
    const float n1 = fmaf(mk[0], s1,   a[1] + a[0]) * pl.x; // s=8l+1 (k=4l)
    const float n2 = (a[2] + a[1]) * pbk;                   // s=8l+2
    const float n3 = fmaf(mk[1], a[1], a[3] + a[2]) * pl.y; // s=8l+3 (k=4l+1)
    const float n4 = (a[4] + a[3]) * pbk;                   // s=8l+4
    const float n5 = fmaf(mk[2], a[3], a[5] + a[4]) * pl.z; // s=8l+5 (k=4l+2)
    const float n6 = (a[6] + a[5]) * pbk;                   // s=8l+6
    const float n7 = fmaf(mk[3], a[5], a[7] + a[6]) * pl.w; // s=8l+7 (k=4l+3)
    const float n8 = (a[8] + a[7]) * pbk;                   // s=256 on lane 31
    a[0] = n0; a[1] = n1; a[2] = n2; a[3] = n3; a[4] = n4;
    a[5] = n5; a[6] = n6; a[7] = n7; a[8] = n8;
}

__global__ void __launch_bounds__(32) ctc_alpha_kernel(
    const int* __restrict__ h_lens, const int* __restrict__ ys,
    const int* __restrict__ ys_lens)
{
    const int b    = blockIdx.x;
    const int lane = threadIdx.x;
    int Tb = h_lens[b];
    if (Tb > CT) Tb = CT;
    const float* pb = g_p + (size_t)b * CT * PSTR;

    // skip masks: odd state s=2k+1 skips iff k>=1 && ys[k]!=ys[k-1]
    float mk[4];
    #pragma unroll
    for (int j = 0; j < 4; ++j) {
        const int k = 4 * lane + j;
        mk[j] = (k >= 1 && ys[b * CL + k] != ys[b * CL + k - 1]) ? 1.f : 0.f;
    }

    // alpha at t=0
    float a[9];
    #pragma unroll
    for (int j = 0; j < 9; ++j) a[j] = 0.f;
    if (lane == 0) { a[0] = pb[0]; a[1] = pb[4]; }

    int Eacc = 0;   // true = stored * 2^Eacc  (identical in every lane)

    // renorm: scale warp max to biased exponent 245 (~2^118), exact pow2.
    // scale 2^d applied as 2^(d/2) * 2^(d - d/2) so each factor is normal.
    #define RENORM()                                                          \
    {                                                                         \
        float m = a[0];                                                       \
        _Pragma("unroll")                                                     \
        for (int j = 1; j < 9; ++j) m = fmaxf(m, a[j]);                       \
        const int e = (int)(__reduce_max_sync(FULLM, __float_as_uint(m)) >> 23); \
        if (e > 0) {                                                          \
            const int d  = 245 - e;                                           \
            const int d1 = d >> 1;                                            \
            const float sc1 = __uint_as_float((unsigned)(d1 + 127) << 23);    \
            const float sc2 = __uint_as_float((unsigned)(d - d1 + 127) << 23);\
            _Pragma("unroll")                                                 \
            for (int j = 0; j < 9; ++j) a[j] = (a[j] * sc1) * sc2;            \
            Eacc -= d;                                                        \
        }                                                                     \
    }

    // 8-step double buffer
    float4 curL[8], nxtL[8];
    float  curB[8], nxtB[8];
    #pragma unroll
    for (int k = 0; k < 8; ++k) {
        int t = 1 + k; if (t > CT - 1) t = CT - 1;
        const float* r = pb + (size_t)t * PSTR;
        curL[k] = reinterpret_cast<const float4*>(r + 4)[lane];
        curB[k] = r[0];
    }

    for (int t0 = 1; t0 < Tb; t0 += 8) {
        // prefetch next chunk
        #pragma unroll
        for (int k = 0; k < 8; ++k) {
            int t = t0 + 8 + k; if (t > CT - 1) t = CT - 1;
            const float* r = pb + (size_t)t * PSTR;
            nxtL[k] = reinterpret_cast<const float4*>(r + 4)[lane];
            nxtB[k] = r[0];
        }

        // 8 recursion steps, renorm after steps 4 and 8
        #pragma unroll
        for (int k = 0; k < 8; ++k) {
            if (t0 + k < Tb) step_f(a, curL[k], curB[k], mk, lane);
            if (k == 3 || k == 7) RENORM();
        }

        #pragma unroll
        for (int k = 0; k < 8; ++k) { curL[k] = nxtL[k]; curB[k] = nxtB[k]; }
    }
    #undef RENORM

    // final: loss = -( log(alpha[2L]) (+) log(alpha[2L-1]) ) / L
    __shared__ float sm[CS];
    #pragma unroll
    for (int j = 0; j < 8; ++j) sm[8 * lane + j] = a[j];
    if (lane == 31) sm[256] = a[8];
    __syncwarp();
    if (lane == 0) {
        const int s_b = 2 * ys_lens[b];
        const int s_l = s_b - 1;
        const float mb = sm[s_b], ml = sm[s_l];
        const double LN2 = 0.6931471805599453;
        const double E  = (double)Eacc * LN2;
        double la = (mb > 0.f) ? log((double)mb) + E : -1e300;
        double lb = (ml > 0.f) ? log((double)ml) + E : -1e300;
        const double mx  = fmax(la, lb);
        const double res = mx + log(exp(la - mx) + exp(lb - mx));
        g_loss[b] = (float)(-res / (double)ys_lens[b]);
    }
}

// ---------------------------------------------------------------------------
// Kernel 3: mean over batch -> scalar output
// ---------------------------------------------------------------------------
__global__ void ctc_reduce_kernel(float* __restrict__ out)
{
    float v = (threadIdx.x < CB) ? g_loss[threadIdx.x] : 0.f;
    #pragma unroll
    for (int o = 16; o > 0; o >>= 1)
        v += __shfl_xor_sync(FULLM, v, o);
    if (threadIdx.x == 0) out[0] = v / (float)CB;
}

extern "C" void kernel_launch(void* const* d_in, const int* in_sizes, int n_in,
                              void* d_out, int out_size)
{
    const float* hs      = (const float*)d_in[0];  // (B, T, V)
    const int*   h_lens  = (const int*)  d_in[1];  // (B,)
    const int*   ys      = (const int*)  d_in[2];  // (B, L)
    const int*   ys_lens = (const int*)  d_in[3];  // (B,)
    float*       out     = (float*)      d_out;

    ctc_p_kernel<<<CB * CT / 8, 256>>>(hs, ys);
    ctc_alpha_kernel<<<CB, 32>>>(h_lens, ys, ys_lens);
    ctc_reduce_kernel<<<1, 32>>>(out);
}

// round 9
// speedup vs baseline: 9.1605x; 1.0240x over previous
#include <cuda_runtime.h>
#include <cuda_bf16.h>
#include <cstdint>
#include <math.h>

// Problem constants (CTC_72000831750194): B=32, T=1000, V=1024, L=128
#define CB 32
#define CT 1000
#define CV 1024
#define CL 128
#define CS (2 * CL + 1)   // 257
#define PSTR 132          // per-(b,t) row: [p_blank, pad, pad, pad, p_lab0..p_lab127]
#define FULLM 0xffffffffu

// Scratch (allocation-free rule: __device__ globals)
__device__ float g_p[(size_t)CB * CT * PSTR];
__device__ float g_loss[CB];

// ---------------------------------------------------------------------------
// Kernel 1: warp-per-row softmax (stable since R3: ~26us, 68% DRAM).
// ---------------------------------------------------------------------------
__global__ void __launch_bounds__(256) ctc_p_kernel(
    const float* __restrict__ hs, const int* __restrict__ ys)
{
    const int warp = threadIdx.x >> 5;
    const int lane = threadIdx.x & 31;
    const int row  = blockIdx.x * 8 + warp;      // grid = B*T/8
    const int b    = row / CT;

    const float*  rp  = hs + (size_t)row * CV;
    const float4* rp4 = reinterpret_cast<const float4*>(rp);

    float4 v[8];
    #pragma unroll
    for (int i = 0; i < 8; ++i) v[i] = rp4[i * 32 + lane];

    float m = -1e30f;
    #pragma unroll
    for (int i = 0; i < 8; ++i)
        m = fmaxf(m, fmaxf(fmaxf(v[i].x, v[i].y), fmaxf(v[i].z, v[i].w)));
    #pragma unroll
    for (int o = 16; o > 0; o >>= 1)
        m = fmaxf(m, __shfl_xor_sync(FULLM, m, o));

    float s = 0.f;
    #pragma unroll
    for (int i = 0; i < 8; ++i)
        s += __expf(v[i].x - m) + __expf(v[i].y - m) +
             __expf(v[i].z - m) + __expf(v[i].w - m);
    #pragma unroll
    for (int o = 16; o > 0; o >>= 1)
        s += __shfl_xor_sync(FULLM, s, o);

    const float inv = 1.0f / s;

    float* op = g_p + (size_t)row * PSTR;
    #pragma unroll
    for (int c = 0; c < 4; ++c) {
        const int k   = c * 32 + lane;
        const int lab = ys[b * CL + k];
        op[4 + k] = __expf(rp[lab] - m) * inv;
    }
    if (lane == 0) op[0] = __expf(rp[0] - m) * inv;
}

// ---------------------------------------------------------------------------
// Kernel 2: alpha recursion (R6-proven math, bit-identical order), fp32
// linear domain, global warp frame anchored at ~2^118, renorm every 4 steps.
// One warp per batch element. Lane l owns states 8l..8l+7 (a[0..7]); lane 31
// also owns state 256 (a[8]).
// NEW vs R6: triple-buffered row prefetch (2 chunks = 16 steps of lead) so
// L2 latency (~234-262cyc) is fully covered for the single warp.
// ---------------------------------------------------------------------------
__device__ __forceinline__ void step_fwd(
    float a[9], float4 pl, float pbk, const float mk[4], int lane)
{
    float s1 = __shfl_up_sync(FULLM, a[7], 1);   // old state 8l-1
    if (lane == 0) s1 = 0.f;

    const float n0 = (a[0] + s1) * pbk;
    const float n1 = fmaf(mk[0], s1,   a[1] + a[0]) * pl.x;
    const float n2 = (a[2] + a[1]) * pbk;
    const float n3 = fmaf(mk[1], a[1], a[3] + a[2]) * pl.y;
    const float n4 = (a[4] + a[3]) * pbk;
    const float n5 = fmaf(mk[2], a[3], a[5] + a[4]) * pl.z;
    const float n6 = (a[6] + a[5]) * pbk;
    const float n7 = fmaf(mk[3], a[5], a[7] + a[6]) * pl.w;
    const float n8 = (a[8] + a[7]) * pbk;        // state 256 on lane 31
    a[0] = n0; a[1] = n1; a[2] = n2; a[3] = n3; a[4] = n4;
    a[5] = n5; a[6] = n6; a[7] = n7; a[8] = n8;
}

// renorm warp max to biased exponent 245 (~2^118); exact power-of-two scale
#define RENORM(a, Eacc)                                                       \
{                                                                             \
    float _m = a[0];                                                          \
    _Pragma("unroll")                                                         \
    for (int _j = 1; _j < 9; ++_j) _m = fmaxf(_m, a[_j]);                     \
    const int _e = (int)(__reduce_max_sync(FULLM, __float_as_uint(_m)) >> 23);\
    if (_e > 0) {                                                             \
        const int _d  = 245 - _e;                                             \
        const int _d1 = _d >> 1;                                              \
        const float _s1 = __uint_as_float((unsigned)(_d1 + 127) << 23);       \
        const float _s2 = __uint_as_float((unsigned)(_d - _d1 + 127) << 23);  \
        _Pragma("unroll")                                                     \
        for (int _j = 0; _j < 9; ++_j) a[_j] = (a[_j] * _s1) * _s2;           \
        Eacc -= _d;                                                           \
    }                                                                         \
}

__global__ void __launch_bounds__(32) ctc_alpha_kernel(
    const int* __restrict__ h_lens, const int* __restrict__ ys,
    const int* __restrict__ ys_lens)
{
    const int b    = blockIdx.x;
    const int lane = threadIdx.x;
    int Tb = h_lens[b];
    if (Tb > CT) Tb = CT;
    const float* pb = g_p + (size_t)b * CT * PSTR;

    // skip masks: odd state s=2k+1 skips iff k>=1 && ys[k]!=ys[k-1]
    float mk[4];
    #pragma unroll
    for (int j = 0; j < 4; ++j) {
        const int k = 4 * lane + j;
        mk[j] = (k >= 1 && ys[b * CL + k] != ys[b * CL + k - 1]) ? 1.f : 0.f;
    }

    // alpha at t=0
    float a[9];
    #pragma unroll
    for (int j = 0; j < 9; ++j) a[j] = 0.f;
    if (lane == 0) { a[0] = pb[0]; a[1] = pb[4]; }

    int Eacc = 0;   // true = stored * 2^Eacc (identical in every lane)

    #define LOADROW(st, PL, PB)                                               \
    {                                                                         \
        int _t = (st); if (_t > CT - 1) _t = CT - 1;                          \
        const float* _r = pb + (size_t)_t * PSTR;                             \
        PL = reinterpret_cast<const float4*>(_r + 4)[lane];                   \
        PB = _r[0];                                                           \
    }

    // triple buffer: cur = rows t0..t0+7, nxt = +8, nx2 prefetched = +16
    float4 curL[8], nxtL[8], nx2L[8];
    float  curB[8], nxtB[8], nx2B[8];
    #pragma unroll
    for (int k = 0; k < 8; ++k) LOADROW(1 + k, curL[k], curB[k]);
    #pragma unroll
    for (int k = 0; k < 8; ++k) LOADROW(9 + k, nxtL[k], nxtB[k]);

    for (int t0 = 1; t0 < Tb; t0 += 8) {
        // issue prefetch for chunk +2 first (16 steps of lead time)
        #pragma unroll
        for (int k = 0; k < 8; ++k) LOADROW(t0 + 16 + k, nx2L[k], nx2B[k]);

        // 8 recursion steps, renorm after steps 4 and 8 (bit-identical to R6)
        #pragma unroll
        for (int k = 0; k < 8; ++k) {
            if (t0 + k < Tb) step_fwd(a, curL[k], curB[k], mk, lane);
            if (k == 3 || k == 7) RENORM(a, Eacc);
        }

        // rotate buffers
        #pragma unroll
        for (int k = 0; k < 8; ++k) {
            curL[k] = nxtL[k]; curB[k] = nxtB[k];
            nxtL[k] = nx2L[k]; nxtB[k] = nx2B[k];
        }
    }
    #undef LOADROW

    // final: loss = -( log(alpha[2L]) (+) log(alpha[2L-1]) ) / L
    __shared__ float sm[CS];
    #pragma unroll
    for (int j = 0; j < 8; ++j) sm[8 * lane + j] = a[j];
    if (lane == 31) sm[256] = a[8];
    __syncwarp();
    if (lane == 0) {
        const int s_b = 2 * ys_lens[b];
        const int s_l = s_b - 1;
        const float mb = sm[s_b], ml = sm[s_l];
        const double LN2 = 0.6931471805599453;
        const double E  = (double)Eacc * LN2;
        double la = (mb > 0.f) ? log((double)mb) + E : -1e300;
        double lb = (ml > 0.f) ? log((double)ml) + E : -1e300;
        const double mx  = fmax(la, lb);
        const double res = mx + log(exp(la - mx) + exp(lb - mx));
        g_loss[b] = (float)(-res / (double)ys_lens[b]);
    }
}

// ---------------------------------------------------------------------------
// Kernel 3: mean over batch -> scalar output
// ---------------------------------------------------------------------------
__global__ void ctc_reduce_kernel(float* __restrict__ out)
{
    float v = (threadIdx.x < CB) ? g_loss[threadIdx.x] : 0.f;
    #pragma unroll
    for (int o = 16; o > 0; o >>= 1)
        v += __shfl_xor_sync(FULLM, v, o);
    if (threadIdx.x == 0) out[0] = v / (float)CB;
}

extern "C" void kernel_launch(void* const* d_in, const int* in_sizes, int n_in,
                              void* d_out, int out_size)
{
    const float* hs      = (const float*)d_in[0];  // (B, T, V)
    const int*   h_lens  = (const int*)  d_in[1];  // (B,)
    const int*   ys      = (const int*)  d_in[2];  // (B, L)
    const int*   ys_lens = (const int*)  d_in[3];  // (B,)
    float*       out     = (float*)      d_out;

    ctc_p_kernel<<<CB * CT / 8, 256>>>(hs, ys);
    ctc_alpha_kernel<<<CB, 32>>>(h_lens, ys, ys_lens);
    ctc_reduce_kernel<<<1, 32>>>(out);
}

// round 10
// speedup vs baseline: 9.4757x; 1.0344x over previous
#include <cuda_runtime.h>
#include <cuda_bf16.h>
#include <cstdint>
#include <math.h>

// Problem constants (CTC_72000831750194): B=32, T=1000, V=1024, L=128
#define CB 32
#define CT 1000
#define CV 1024
#define CL 128
#define CS (2 * CL + 1)   // 257
#define PSTR 132          // per-(b,t) row: [p_blank, pad, pad, pad, p_lab0..p_lab127]
#define FULLM 0xffffffffu

// Scratch (allocation-free rule: __device__ globals)
__device__ float g_p[(size_t)CB * CT * PSTR];
__device__ float g_loss[CB];

// ---------------------------------------------------------------------------
// Kernel 1: warp-per-row softmax (stable since R3: ~26-27us, ~66% DRAM).
// ---------------------------------------------------------------------------
__global__ void __launch_bounds__(256) ctc_p_kernel(
    const float* __restrict__ hs, const int* __restrict__ ys)
{
    const int warp = threadIdx.x >> 5;
    const int lane = threadIdx.x & 31;
    const int row  = blockIdx.x * 8 + warp;      // grid = B*T/8
    const int b    = row / CT;

    const float*  rp  = hs + (size_t)row * CV;
    const float4* rp4 = reinterpret_cast<const float4*>(rp);

    float4 v[8];
    #pragma unroll
    for (int i = 0; i < 8; ++i) v[i] = rp4[i * 32 + lane];

    float m = -1e30f;
    #pragma unroll
    for (int i = 0; i < 8; ++i)
        m = fmaxf(m, fmaxf(fmaxf(v[i].x, v[i].y), fmaxf(v[i].z, v[i].w)));
    #pragma unroll
    for (int o = 16; o > 0; o >>= 1)
        m = fmaxf(m, __shfl_xor_sync(FULLM, m, o));

    float s = 0.f;
    #pragma unroll
    for (int i = 0; i < 8; ++i)
        s += __expf(v[i].x - m) + __expf(v[i].y - m) +
             __expf(v[i].z - m) + __expf(v[i].w - m);
    #pragma unroll
    for (int o = 16; o > 0; o >>= 1)
        s += __shfl_xor_sync(FULLM, s, o);

    const float inv = 1.0f / s;

    float* op = g_p + (size_t)row * PSTR;
    #pragma unroll
    for (int c = 0; c < 4; ++c) {
        const int k   = c * 32 + lane;
        const int lab = ys[b * CL + k];
        op[4 + k] = __expf(rp[lab] - m) * inv;
    }
    if (lane == 0) op[0] = __expf(rp[0] - m) * inv;
}

// ---------------------------------------------------------------------------
// Kernel 2: alpha recursion — R6/R9-proven math, BIT-IDENTICAL trajectory.
// fp32 linear domain, warp frame anchored ~2^118, renorm every 4 steps.
// One warp per batch element. Lane l owns states 8l..8l+7 (a[0..7]); lane 31
// also owns state 256 (a[8]).
// R10: 3-phase ping-pong (no buffer-rotation MOVs), tree local max,
// single-multiply renorm fast path (exact power-of-two scaling).
// ---------------------------------------------------------------------------
__device__ __forceinline__ void step_fwd(
    float a[9], float4 pl, float pbk, const float mk[4], int lane)
{
    float s1 = __shfl_up_sync(FULLM, a[7], 1);   // old state 8l-1
    if (lane == 0) s1 = 0.f;

    const float n0 = (a[0] + s1) * pbk;
    const float n1 = fmaf(mk[0], s1,   a[1] + a[0]) * pl.x;
    const float n2 = (a[2] + a[1]) * pbk;
    const float n3 = fmaf(mk[1], a[1], a[3] + a[2]) * pl.y;
    const float n4 = (a[4] + a[3]) * pbk;
    const float n5 = fmaf(mk[2], a[3], a[5] + a[4]) * pl.z;
    const float n6 = (a[6] + a[5]) * pbk;
    const float n7 = fmaf(mk[3], a[5], a[7] + a[6]) * pl.w;
    const float n8 = (a[8] + a[7]) * pbk;        // state 256 on lane 31
    a[0] = n0; a[1] = n1; a[2] = n2; a[3] = n3; a[4] = n4;
    a[5] = n5; a[6] = n6; a[7] = n7; a[8] = n8;
}

// renorm warp max to biased exponent 245 (~2^118); exact power-of-two scale.
// Tree max (same e as serial — max is exact); single mul when 2^d is
// representable (always in steady state: d in [-9, ~50]); double mul fallback.
#define RENORM(a, Eacc)                                                       \
{                                                                             \
    const float _m01 = fmaxf(a[0], a[1]);                                     \
    const float _m23 = fmaxf(a[2], a[3]);                                     \
    const float _m45 = fmaxf(a[4], a[5]);                                     \
    const float _m67 = fmaxf(a[6], a[7]);                                     \
    const float _m03 = fmaxf(_m01, _m23);                                     \
    const float _m47 = fmaxf(_m45, _m67);                                     \
    const float _m   = fmaxf(fmaxf(_m03, _m47), a[8]);                        \
    const int _e = (int)(__reduce_max_sync(FULLM, __float_as_uint(_m)) >> 23);\
    if (_e > 0) {                                                             \
        const int _d = 245 - _e;                                              \
        if (_d <= 127) {                                                      \
            const float _sc = __uint_as_float((unsigned)(_d + 127) << 23);    \
            _Pragma("unroll")                                                 \
            for (int _j = 0; _j < 9; ++_j) a[_j] *= _sc;                      \
        } else {                                                              \
            const int _d1 = _d >> 1;                                          \
            const float _s1 = __uint_as_float((unsigned)(_d1 + 127) << 23);   \
            const float _s2 = __uint_as_float((unsigned)(_d - _d1 + 127) << 23);\
            _Pragma("unroll")                                                 \
            for (int _j = 0; _j < 9; ++_j) a[_j] = (a[_j] * _s1) * _s2;       \
        }                                                                     \
        Eacc -= _d;                                                           \
    }                                                                         \
}

__global__ void __launch_bounds__(32) ctc_alpha_kernel(
    const int* __restrict__ h_lens, const int* __restrict__ ys,
    const int* __restrict__ ys_lens)
{
    const int b    = blockIdx.x;
    const int lane = threadIdx.x;
    int Tb = h_lens[b];
    if (Tb > CT) Tb = CT;
    const float* pb = g_p + (size_t)b * CT * PSTR;

    // skip masks: odd state s=2k+1 skips iff k>=1 && ys[k]!=ys[k-1]
    float mk[4];
    #pragma unroll
    for (int j = 0; j < 4; ++j) {
        const int k = 4 * lane + j;
        mk[j] = (k >= 1 && ys[b * CL + k] != ys[b * CL + k - 1]) ? 1.f : 0.f;
    }

    // alpha at t=0
    float a[9];
    #pragma unroll
    for (int j = 0; j < 9; ++j) a[j] = 0.f;
    if (lane == 0) { a[0] = pb[0]; a[1] = pb[4]; }

    int Eacc = 0;   // true = stored * 2^Eacc (identical in every lane)

    #define LOADROW(st, PL, PB)                                               \
    {                                                                         \
        int _t = (st); if (_t > CT - 1) _t = CT - 1;                          \
        const float* _r = pb + (size_t)_t * PSTR;                             \
        PL = reinterpret_cast<const float4*>(_r + 4)[lane];                   \
        PB = _r[0];                                                           \
    }

    // 3 buffers used in rotating ROLES (no data movement between them)
    float4 L0[8], L1[8], L2[8];
    float  B0[8], B1[8], B2[8];
    #pragma unroll
    for (int k = 0; k < 8; ++k) LOADROW(1 + k, L0[k], B0[k]);
    #pragma unroll
    for (int k = 0; k < 8; ++k) LOADROW(9 + k, L1[k], B1[k]);

    // one phase: prefetch 8 rows into PBUF (S+16..S+23), run steps S..S+7
    // from CBUF with per-step guards, renorm after steps 4 and 8 (d=0 no-op
    // when the group ran empty -> trajectory identical to the 8-step loop).
    #define PHASE(CL_, CB_, PL_, PB_, S)                                      \
    {                                                                         \
        _Pragma("unroll")                                                     \
        for (int _k = 0; _k < 8; ++_k) LOADROW((S) + 16 + _k, PL_[_k], PB_[_k]); \
        _Pragma("unroll")                                                     \
        for (int _k = 0; _k < 8; ++_k) {                                      \
            if ((S) + _k < Tb) step_fwd(a, CL_[_k], CB_[_k], mk, lane);       \
            if (_k == 3 || _k == 7) RENORM(a, Eacc);                          \
        }                                                                     \
    }

    for (int t0 = 1; t0 < Tb; t0 += 24) {
        PHASE(L0, B0, L2, B2, t0)
        PHASE(L1, B1, L0, B0, t0 + 8)
        PHASE(L2, B2, L1, B1, t0 + 16)
    }
    #undef PHASE
    #undef LOADROW

    // final: loss = -( log(alpha[2L]) (+) log(alpha[2L-1]) ) / L
    __shared__ float sm[CS];
    #pragma unroll
    for (int j = 0; j < 8; ++j) sm[8 * lane + j] = a[j];
    if (lane == 31) sm[256] = a[8];
    __syncwarp();
    if (lane == 0) {
        const int s_b = 2 * ys_lens[b];
        const int s_l = s_b - 1;
        const float mb = sm[s_b], ml = sm[s_l];
        const double LN2 = 0.6931471805599453;
        const double E  = (double)Eacc * LN2;
        double la = (mb > 0.f) ? log((double)mb) + E : -1e300;
        double lb = (ml > 0.f) ? log((double)ml) + E : -1e300;
        const double mx  = fmax(la, lb);
        const double res = mx + log(exp(la - mx) + exp(lb - mx));
        g_loss[b] = (float)(-res / (double)ys_lens[b]);
    }
}

// ---------------------------------------------------------------------------
// Kernel 3: mean over batch -> scalar output
// ---------------------------------------------------------------------------
__global__ void ctc_reduce_kernel(float* __restrict__ out)
{
    float v = (threadIdx.x < CB) ? g_loss[threadIdx.x] : 0.f;
    #pragma unroll
    for (int o = 16; o > 0; o >>= 1)
        v += __shfl_xor_sync(FULLM, v, o);
    if (threadIdx.x == 0) out[0] = v / (float)CB;
}

extern "C" void kernel_launch(void* const* d_in, const int* in_sizes, int n_in,
                              void* d_out, int out_size)
{
    const float* hs      = (const float*)d_in[0];  // (B, T, V)
    const int*   h_lens  = (const int*)  d_in[1];  // (B,)
    const int*   ys      = (const int*)  d_in[2];  // (B, L)
    const int*   ys_lens = (const int*)  d_in[3];  // (B,)
    float*       out     = (float*)      d_out;

    ctc_p_kernel<<<CB * CT / 8, 256>>>(hs, ys);
    ctc_alpha_kernel<<<CB, 32>>>(h_lens, ys, ys_lens);
    ctc_reduce_kernel<<<1, 32>>>(out);
}

// round 11
// speedup vs baseline: 9.9475x; 1.0498x over previous
#include <cuda_runtime.h>
#include <cuda_bf16.h>
#include <cstdint>
#include <math.h>

// Problem constants (CTC_72000831750194): B=32, T=1000, V=1024, L=128
#define CB 32
#define CT 1000
#define CV 1024
#define CL 128
#define CS (2 * CL + 1)   // 257
#define PSTR 132          // per-(b,t) row: [p_blank, pad, pad, pad, p_lab0..p_lab127]
#define FULLM 0xffffffffu

// Scratch (allocation-free rule: __device__ globals)
__device__ float g_p[(size_t)CB * CT * PSTR];
__device__ float g_loss[CB];

// ---------------------------------------------------------------------------
// Kernel 1: warp-per-row softmax (stable since R3: ~26us, ~68% DRAM).
// ---------------------------------------------------------------------------
__global__ void __launch_bounds__(256) ctc_p_kernel(
    const float* __restrict__ hs, const int* __restrict__ ys)
{
    const int warp = threadIdx.x >> 5;
    const int lane = threadIdx.x & 31;
    const int row  = blockIdx.x * 8 + warp;      // grid = B*T/8
    const int b    = row / CT;

    const float*  rp  = hs + (size_t)row * CV;
    const float4* rp4 = reinterpret_cast<const float4*>(rp);

    float4 v[8];
    #pragma unroll
    for (int i = 0; i < 8; ++i) v[i] = rp4[i * 32 + lane];

    float m = -1e30f;
    #pragma unroll
    for (int i = 0; i < 8; ++i)
        m = fmaxf(m, fmaxf(fmaxf(v[i].x, v[i].y), fmaxf(v[i].z, v[i].w)));
    #pragma unroll
    for (int o = 16; o > 0; o >>= 1)
        m = fmaxf(m, __shfl_xor_sync(FULLM, m, o));

    float s = 0.f;
    #pragma unroll
    for (int i = 0; i < 8; ++i)
        s += __expf(v[i].x - m) + __expf(v[i].y - m) +
             __expf(v[i].z - m) + __expf(v[i].w - m);
    #pragma unroll
    for (int o = 16; o > 0; o >>= 1)
        s += __shfl_xor_sync(FULLM, s, o);

    const float inv = 1.0f / s;

    float* op = g_p + (size_t)row * PSTR;
    #pragma unroll
    for (int c = 0; c < 4; ++c) {
        const int k   = c * 32 + lane;
        const int lab = ys[b * CL + k];
        op[4 + k] = __expf(rp[lab] - m) * inv;
    }
    if (lane == 0) op[0] = __expf(rp[0] - m) * inv;
}

// ---------------------------------------------------------------------------
// Kernel 2: alpha recursion — proven math, BIT-IDENTICAL trajectory to R6-R10.
// fp32 linear domain, warp frame anchored ~2^118, renorm every 4 steps.
// One warp per batch element. Lane l owns states 8l..8l+7 (a[0..7]); lane 31
// also owns state 256 (a[8]).
// R11: branchless main loop (full 24-step triples, NO per-step guards ->
// no BSSY/BSYNC reconvergence envelopes on the critical path); guarded tail
// handles the final <24 steps with the R10 code.
// ---------------------------------------------------------------------------
__device__ __forceinline__ void step_fwd(
    float a[9], float4 pl, float pbk, const float mk[4], int lane)
{
    float s1 = __shfl_up_sync(FULLM, a[7], 1);   // old state 8l-1
    if (lane == 0) s1 = 0.f;

    const float n0 = (a[0] + s1) * pbk;
    const float n1 = fmaf(mk[0], s1,   a[1] + a[0]) * pl.x;
    const float n2 = (a[2] + a[1]) * pbk;
    const float n3 = fmaf(mk[1], a[1], a[3] + a[2]) * pl.y;
    const float n4 = (a[4] + a[3]) * pbk;
    const float n5 = fmaf(mk[2], a[3], a[5] + a[4]) * pl.z;
    const float n6 = (a[6] + a[5]) * pbk;
    const float n7 = fmaf(mk[3], a[5], a[7] + a[6]) * pl.w;
    const float n8 = (a[8] + a[7]) * pbk;        // state 256 on lane 31
    a[0] = n0; a[1] = n1; a[2] = n2; a[3] = n3; a[4] = n4;
    a[5] = n5; a[6] = n6; a[7] = n7; a[8] = n8;
}

// renorm warp max to biased exponent 245 (~2^118); exact power-of-two scale.
#define RENORM(a, Eacc)                                                       \
{                                                                             \
    const float _m01 = fmaxf(a[0], a[1]);                                     \
    const float _m23 = fmaxf(a[2], a[3]);                                     \
    const float _m45 = fmaxf(a[4], a[5]);                                     \
    const float _m67 = fmaxf(a[6], a[7]);                                     \
    const float _m03 = fmaxf(_m01, _m23);                                     \
    const float _m47 = fmaxf(_m45, _m67);                                     \
    const float _m   = fmaxf(fmaxf(_m03, _m47), a[8]);                        \
    const int _e = (int)(__reduce_max_sync(FULLM, __float_as_uint(_m)) >> 23);\
    if (_e > 0) {                                                             \
        const int _d = 245 - _e;                                              \
        if (_d <= 127) {                                                      \
            const float _sc = __uint_as_float((unsigned)(_d + 127) << 23);    \
            _Pragma("unroll")                                                 \
            for (int _j = 0; _j < 9; ++_j) a[_j] *= _sc;                      \
        } else {                                                              \
            const int _d1 = _d >> 1;                                          \
            const float _s1 = __uint_as_float((unsigned)(_d1 + 127) << 23);   \
            const float _s2 = __uint_as_float((unsigned)(_d - _d1 + 127) << 23);\
            _Pragma("unroll")                                                 \
            for (int _j = 0; _j < 9; ++_j) a[_j] = (a[_j] * _s1) * _s2;       \
        }                                                                     \
        Eacc -= _d;                                                           \
    }                                                                         \
}

__global__ void __launch_bounds__(32) ctc_alpha_kernel(
    const int* __restrict__ h_lens, const int* __restrict__ ys,
    const int* __restrict__ ys_lens)
{
    const int b    = blockIdx.x;
    const int lane = threadIdx.x;
    int Tb = h_lens[b];
    if (Tb > CT) Tb = CT;
    const float* pb = g_p + (size_t)b * CT * PSTR;

    // skip masks: odd state s=2k+1 skips iff k>=1 && ys[k]!=ys[k-1]
    float mk[4];
    #pragma unroll
    for (int j = 0; j < 4; ++j) {
        const int k = 4 * lane + j;
        mk[j] = (k >= 1 && ys[b * CL + k] != ys[b * CL + k - 1]) ? 1.f : 0.f;
    }

    // alpha at t=0
    float a[9];
    #pragma unroll
    for (int j = 0; j < 9; ++j) a[j] = 0.f;
    if (lane == 0) { a[0] = pb[0]; a[1] = pb[4]; }

    int Eacc = 0;   // true = stored * 2^Eacc (identical in every lane)

    #define LOADROW(st, PL, PB)                                               \
    {                                                                         \
        int _t = (st); if (_t > CT - 1) _t = CT - 1;                          \
        const float* _r = pb + (size_t)_t * PSTR;                             \
        PL = reinterpret_cast<const float4*>(_r + 4)[lane];                   \
        PB = _r[0];                                                           \
    }

    // 3 buffers used in rotating ROLES (no data movement between them)
    float4 L0[8], L1[8], L2[8];
    float  B0[8], B1[8], B2[8];
    #pragma unroll
    for (int k = 0; k < 8; ++k) LOADROW(1 + k, L0[k], B0[k]);
    #pragma unroll
    for (int k = 0; k < 8; ++k) LOADROW(9 + k, L1[k], B1[k]);

    // branchless phase: no per-step guards (only valid when all 8 steps run)
    #define PHASE_FAST(CL_, CB_, PL_, PB_, S)                                 \
    {                                                                         \
        _Pragma("unroll")                                                     \
        for (int _k = 0; _k < 8; ++_k) LOADROW((S) + 16 + _k, PL_[_k], PB_[_k]); \
        _Pragma("unroll")                                                     \
        for (int _k = 0; _k < 8; ++_k) {                                      \
            step_fwd(a, CL_[_k], CB_[_k], mk, lane);                          \
            if (_k == 3 || _k == 7) RENORM(a, Eacc);                          \
        }                                                                     \
    }

    // guarded phase (tail only): identical math, per-step guard
    #define PHASE_TAIL(CL_, CB_, PL_, PB_, S)                                 \
    {                                                                         \
        _Pragma("unroll")                                                     \
        for (int _k = 0; _k < 8; ++_k) LOADROW((S) + 16 + _k, PL_[_k], PB_[_k]); \
        _Pragma("unroll")                                                     \
        for (int _k = 0; _k < 8; ++_k) {                                      \
            if ((S) + _k < Tb) step_fwd(a, CL_[_k], CB_[_k], mk, lane);       \
            if (_k == 3 || _k == 7) RENORM(a, Eacc);                          \
        }                                                                     \
    }

    int t0 = 1;
    for (; t0 + 24 <= Tb; t0 += 24) {        // all 24 steps valid: t0+23 < Tb
        PHASE_FAST(L0, B0, L2, B2, t0)
        PHASE_FAST(L1, B1, L0, B0, t0 + 8)
        PHASE_FAST(L2, B2, L1, B1, t0 + 16)
    }
    for (; t0 < Tb; t0 += 24) {              // final partial triple
        PHASE_TAIL(L0, B0, L2, B2, t0)
        PHASE_TAIL(L1, B1, L0, B0, t0 + 8)
        PHASE_TAIL(L2, B2, L1, B1, t0 + 16)
    }
    #undef PHASE_FAST
    #undef PHASE_TAIL
    #undef LOADROW

    // final: loss = -( log(alpha[2L]) (+) log(alpha[2L-1]) ) / L
    __shared__ float sm[CS];
    #pragma unroll
    for (int j = 0; j < 8; ++j) sm[8 * lane + j] = a[j];
    if (lane == 31) sm[256] = a[8];
    __syncwarp();
    if (lane == 0) {
        const int s_b = 2 * ys_lens[b];
        const int s_l = s_b - 1;
        const float mb = sm[s_b], ml = sm[s_l];
        const double LN2 = 0.6931471805599453;
        const double E  = (double)Eacc * LN2;
        double la = (mb > 0.f) ? log((double)mb) + E : -1e300;
        double lb = (ml > 0.f) ? log((double)ml) + E : -1e300;
        const double mx  = fmax(la, lb);
        const double res = mx + log(exp(la - mx) + exp(lb - mx));
        g_loss[b] = (float)(-res / (double)ys_lens[b]);
    }
}

// ---------------------------------------------------------------------------
// Kernel 3: mean over batch -> scalar output
// ---------------------------------------------------------------------------
__global__ void ctc_reduce_kernel(float* __restrict__ out)
{
    float v = (threadIdx.x < CB) ? g_loss[threadIdx.x] : 0.f;
    #pragma unroll
    for (int o = 16; o > 0; o >>= 1)
        v += __shfl_xor_sync(FULLM, v, o);
    if (threadIdx.x == 0) out[0] = v / (float)CB;
}

extern "C" void kernel_launch(void* const* d_in, const int* in_sizes, int n_in,
                              void* d_out, int out_size)
{
    const float* hs      = (const float*)d_in[0];  // (B, T, V)
    const int*   h_lens  = (const int*)  d_in[1];  // (B,)
    const int*   ys      = (const int*)  d_in[2];  // (B, L)
    const int*   ys_lens = (const int*)  d_in[3];  // (B,)
    float*       out     = (float*)      d_out;

    ctc_p_kernel<<<CB * CT / 8, 256>>>(hs, ys);
    ctc_alpha_kernel<<<CB, 32>>>(h_lens, ys, ys_lens);
    ctc_reduce_kernel<<<1, 32>>>(out);
}